// round 10
// baseline (speedup 1.0000x reference)
#include <cuda_runtime.h>
#include <cuda_bf16.h>
#include <math.h>

#define NB 32
#define NN 5000
#define NE 80000
#define CC 64
#define DIN 16
#define KP 30
#define FH 128
#define FTOT 208
#define FLATN (KP*FTOT + 1)   // 6241
#define NTOT ((size_t)NB*NN)  // 160000 rows
#define NNCC ((size_t)NN*CC)
#define BN_EPS 1e-5f

// ---------------- scratch (device globals; no allocation allowed) -------------
// Resolve with cudaGetSymbolAddress before passing to kernels (host shadows!).
__device__ float g_deg[NN];
__device__ float g_dinv[NN];
__device__ int   g_count[NN];
__device__ int   g_cursor[NN];
__device__ int   g_rowptr[NN + 1];
__device__ int   g_csr_col[NE];
__device__ float g_csr_val[NE];

__device__ float g_ax[NB * NN * DIN];  // layer-0 aggregated input (AX)
__device__ float g_xw[NB * NN * CC];   // GEMM output (spmm input)
__device__ float g_h1[NB * NN * CC];   // RAW (pre-BN) conv1 output
__device__ float g_h2[NB * NN * CC];   // RAW (pre-BN) conv2 output
__device__ float g_h3[NB * NN * CC];   // post-relu conv3 output

__device__ double g_bnsum[2 * CC];
__device__ double g_bnsumsq[2 * CC];
__device__ float  g_bnmu[2 * CC];
__device__ float  g_bnsc[2 * CC];
__device__ int    g_bnflag[2];
__device__ float  g_hm[NB * FH];

// ---------------- init: graph scratch + BN slots -----------------------------
__global__ void k_zero() {
    int i = blockIdx.x * blockDim.x + threadIdx.x;
    if (i < NN) { g_deg[i] = 0.f; g_count[i] = 0; g_cursor[i] = 0; }
    if (i < 2 * CC) { g_bnsum[i] = 0.0; g_bnsumsq[i] = 0.0; }
    if (i < 2) g_bnflag[i] = 0;
}

__global__ void k_deg_accum(const float* __restrict__ attr, const int* __restrict__ erow) {
    int e = blockIdx.x * blockDim.x + threadIdx.x;
    if (e < NE) {
        int r = erow[e];
        atomicAdd(&g_deg[r], attr[e]);
        atomicAdd(&g_count[r], 1);
    }
}

// dinv + exclusive scan, single block of 1024
__global__ void k_dinv_scan() {
    __shared__ int s[1024];
    int tid = threadIdx.x;
    for (int i = tid; i < NN; i += 1024) {
        float d = g_deg[i] + 1.0f;  // self loop weight 1
        g_dinv[i] = (d > 0.f) ? rsqrtf(fmaxf(d, 1e-12f)) : 0.f;
    }
    const int CH = 5; // 1024*5 >= 5000
    int base = tid * CH;
    int vals[CH];
    int sum = 0;
    #pragma unroll
    for (int j = 0; j < CH; j++) {
        int idx = base + j;
        int v = (idx < NN) ? g_count[idx] : 0;
        vals[j] = sum;
        sum += v;
    }
    s[tid] = sum;
    __syncthreads();
    for (int off = 1; off < 1024; off <<= 1) {
        int v = (tid >= off) ? s[tid - off] : 0;
        __syncthreads();
        s[tid] += v;
        __syncthreads();
    }
    int excl = (tid == 0) ? 0 : s[tid - 1];
    #pragma unroll
    for (int j = 0; j < CH; j++) {
        int idx = base + j;
        if (idx < NN) g_rowptr[idx] = excl + vals[j];
    }
    if (tid == 1023) g_rowptr[NN] = s[1023];
}

__global__ void k_build_csr(const float* __restrict__ attr,
                            const int* __restrict__ erow,
                            const int* __restrict__ ecol) {
    int e = blockIdx.x * blockDim.x + threadIdx.x;
    if (e < NE) {
        int r = erow[e], c = ecol[e];
        float nv = g_dinv[r] * attr[e] * g_dinv[c];
        int pos = g_rowptr[r] + atomicAdd(&g_cursor[r], 1);
        g_csr_col[pos] = c;
        g_csr_val[pos] = nv;
    }
}

// ---------------- SPMM 16-channel (layer-0 aggregation of raw x) -------------
__global__ void k_spmm16(const float* __restrict__ x, float* __restrict__ ax) {
    int gw = (blockIdx.x * blockDim.x + threadIdx.x) >> 5;
    int lane = threadIdx.x & 31;
    if (gw >= NB * NN || lane >= DIN) return;
    int b = gw / NN;
    int r = gw - b * NN;

    const float* base = x + (size_t)b * NN * DIN;
    float di = g_dinv[r];
    float acc = base[(size_t)r * DIN + lane] * di * di;

    int s = g_rowptr[r];
    int e = g_rowptr[r + 1];
    int i = s;
    for (; i + 4 <= e; i += 4) {
        int   cA = g_csr_col[i + 0], cB = g_csr_col[i + 1];
        int   cC = g_csr_col[i + 2], cD = g_csr_col[i + 3];
        float wA = g_csr_val[i + 0], wB = g_csr_val[i + 1];
        float wC = g_csr_val[i + 2], wD = g_csr_val[i + 3];
        acc += wA * base[(size_t)cA * DIN + lane]
             + wB * base[(size_t)cB * DIN + lane]
             + wC * base[(size_t)cC * DIN + lane]
             + wD * base[(size_t)cD * DIN + lane];
    }
    for (; i < e; i++)
        acc += g_csr_val[i] * base[(size_t)g_csr_col[i] * DIN + lane];
    ax[(size_t)gw * DIN + lane] = acc;
}

// ---------------- shared finalize helper (BN ticket) -------------------------
__device__ __forceinline__ void bn_finalize_ticket(int slot, const float* __restrict__ gam,
                                                   int nblocks) {
    __shared__ int last;
    __syncthreads();
    if (threadIdx.x == 0) {
        __threadfence();
        int t = atomicAdd(&g_bnflag[slot], 1);
        last = (t == nblocks - 1) ? 1 : 0;
    }
    __syncthreads();
    if (last && threadIdx.x < CC) {
        __threadfence();
        const double invN = 1.0 / (double)(NB * NN);
        double mu = g_bnsum[slot * CC + threadIdx.x] * invN;
        double var = g_bnsumsq[slot * CC + threadIdx.x] * invN - mu * mu;
        g_bnmu[slot * CC + threadIdx.x] = (float)mu;
        g_bnsc[slot * CC + threadIdx.x] = rsqrtf((float)var + BN_EPS) * gam[threadIdx.x];
    }
}

// ---------------- dense GEMM (register-blocked): (M,K)@(K,64) -> (M,64) ------
// 256 threads = 16 ch-groups(4ch) x 16 row-slots; each row-slot owns 8 rows.
// BNIN:  apply relu((v-mu)*sc+be) to input elements on load (K==CC).
// BNOUT: accumulate per-channel sum/sumsq of outputs into BN slot_out.
template <int K, bool BIAS, bool BNIN, bool BNOUT>
__global__ void k_gemm_rb(const float* __restrict__ in, const float* __restrict__ W,
                          const float* __restrict__ bias, const float* __restrict__ be,
                          int slot_in, int slot_out, const float* __restrict__ gam,
                          float* __restrict__ out) {
    __shared__ float Ws[K * CC];
    __shared__ float smu[CC], ssc[CC], sbe[CC];
    int tid = threadIdx.x;
    for (int i = tid; i < K * CC; i += 256) Ws[i] = W[i];
    if (BNIN && tid < CC) {
        smu[tid] = g_bnmu[slot_in * CC + tid];
        ssc[tid] = g_bnsc[slot_in * CC + tid];
        sbe[tid] = be[tid];
    }
    __syncthreads();

    int c = (tid & 15) * 4;
    int rslot = tid >> 4;
    size_t m0 = (size_t)blockIdx.x * 128 + (size_t)rslot * 8;

    float4 acc[8];
    #pragma unroll
    for (int r = 0; r < 8; r++) { acc[r].x = 0.f; acc[r].y = 0.f; acc[r].z = 0.f; acc[r].w = 0.f; }

    #pragma unroll
    for (int k = 0; k < K; k += 4) {
        float4 w0 = *(const float4*)(&Ws[(k + 0) * CC + c]);
        float4 w1 = *(const float4*)(&Ws[(k + 1) * CC + c]);
        float4 w2 = *(const float4*)(&Ws[(k + 2) * CC + c]);
        float4 w3 = *(const float4*)(&Ws[(k + 3) * CC + c]);
        float4 mu4, sc4, be4;
        if (BNIN) {
            mu4 = *(const float4*)(&smu[k]);
            sc4 = *(const float4*)(&ssc[k]);
            be4 = *(const float4*)(&sbe[k]);
        }
        #pragma unroll
        for (int r = 0; r < 8; r++) {
            float4 av = *(const float4*)(in + (m0 + r) * K + k);
            if (BNIN) {
                av.x = fmaxf((av.x - mu4.x) * sc4.x + be4.x, 0.f);
                av.y = fmaxf((av.y - mu4.y) * sc4.y + be4.y, 0.f);
                av.z = fmaxf((av.z - mu4.z) * sc4.z + be4.z, 0.f);
                av.w = fmaxf((av.w - mu4.w) * sc4.w + be4.w, 0.f);
            }
            acc[r].x += av.x * w0.x + av.y * w1.x + av.z * w2.x + av.w * w3.x;
            acc[r].y += av.x * w0.y + av.y * w1.y + av.z * w2.y + av.w * w3.y;
            acc[r].z += av.x * w0.z + av.y * w1.z + av.z * w2.z + av.w * w3.z;
            acc[r].w += av.x * w0.w + av.y * w1.w + av.z * w2.w + av.w * w3.w;
        }
    }
    float4 bv = make_float4(0.f, 0.f, 0.f, 0.f);
    if (BIAS) bv = *(const float4*)(bias + c);

    float4 s4 = make_float4(0.f, 0.f, 0.f, 0.f);
    float4 q4 = make_float4(0.f, 0.f, 0.f, 0.f);
    #pragma unroll
    for (int r = 0; r < 8; r++) {
        float4 o;
        o.x = acc[r].x + bv.x; o.y = acc[r].y + bv.y;
        o.z = acc[r].z + bv.z; o.w = acc[r].w + bv.w;
        *(float4*)(out + (m0 + r) * CC + c) = o;
        if (BNOUT) {
            s4.x += o.x; s4.y += o.y; s4.z += o.z; s4.w += o.w;
            q4.x += o.x * o.x; q4.y += o.y * o.y; q4.z += o.z * o.z; q4.w += o.w * o.w;
        }
    }

    if (BNOUT) {
        // reuse Ws as reduction scratch (16 rslots x 64 ch x {sum,sq})
        __syncthreads();
        float* ssum = Ws;             // [16][64]
        float* ssq  = Ws + 16 * 64;   // [16][64]  (K*CC >= 2048 when K==16? no!)
        // K==16 gives Ws 1024 floats; need 2048 -> use dedicated buffers instead.
        __shared__ float rsum[16 * 64];
        __shared__ float rsq[16 * 64];
        (void)ssum; (void)ssq;
        rsum[rslot * 64 + c + 0] = s4.x; rsum[rslot * 64 + c + 1] = s4.y;
        rsum[rslot * 64 + c + 2] = s4.z; rsum[rslot * 64 + c + 3] = s4.w;
        rsq[rslot * 64 + c + 0] = q4.x; rsq[rslot * 64 + c + 1] = q4.y;
        rsq[rslot * 64 + c + 2] = q4.z; rsq[rslot * 64 + c + 3] = q4.w;
        __syncthreads();
        if (tid < CC) {
            float ts = 0.f, tq = 0.f;
            #pragma unroll
            for (int j = 0; j < 16; j++) { ts += rsum[j * 64 + tid]; tq += rsq[j * 64 + tid]; }
            atomicAdd(&g_bnsum[slot_out * CC + tid], (double)ts);
            atomicAdd(&g_bnsumsq[slot_out * CC + tid], (double)tq);
        }
        bn_finalize_ticket(slot_out, gam, gridDim.x);
    }
}

// ---------------- SPMM 64ch, 4 batches per warp ------------------------------
// warp handles (row, batch-group of 4); col/val loads amortized over 4 batches.
// RELU: final relu. BNOUT: accumulate BN stats of outputs into slot.
template <bool RELU, bool BNOUT>
__global__ void k_spmm4(const float* __restrict__ xw, const float* __restrict__ bias,
                        float* __restrict__ out, int slot, const float* __restrict__ gam) {
    int gw = (blockIdx.x * blockDim.x + threadIdx.x) >> 5;  // 0..39999
    int lane = threadIdx.x & 31;
    int warp = threadIdx.x >> 5;                            // 0..7
    int r = gw >> 3;
    int bg = gw & 7;                                        // batch group
    int c0 = lane * 2;

    const float* base = xw + (size_t)(bg * 4) * NNCC;
    float di = g_dinv[r];
    float sl = di * di;

    const float* selfp = base + (size_t)r * CC + c0;
    float2 a0 = *(const float2*)(selfp);
    float2 a1 = *(const float2*)(selfp + NNCC);
    float2 a2 = *(const float2*)(selfp + 2 * NNCC);
    float2 a3 = *(const float2*)(selfp + 3 * NNCC);
    a0.x *= sl; a0.y *= sl; a1.x *= sl; a1.y *= sl;
    a2.x *= sl; a2.y *= sl; a3.x *= sl; a3.y *= sl;

    int s = g_rowptr[r];
    int e = g_rowptr[r + 1];
    int i = s;
    for (; i + 2 <= e; i += 2) {
        int   cA = g_csr_col[i + 0], cB = g_csr_col[i + 1];
        float wA = g_csr_val[i + 0], wB = g_csr_val[i + 1];
        const float* pA = base + (size_t)cA * CC + c0;
        const float* pB = base + (size_t)cB * CC + c0;
        float2 vA0 = *(const float2*)(pA);
        float2 vA1 = *(const float2*)(pA + NNCC);
        float2 vA2 = *(const float2*)(pA + 2 * NNCC);
        float2 vA3 = *(const float2*)(pA + 3 * NNCC);
        float2 vB0 = *(const float2*)(pB);
        float2 vB1 = *(const float2*)(pB + NNCC);
        float2 vB2 = *(const float2*)(pB + 2 * NNCC);
        float2 vB3 = *(const float2*)(pB + 3 * NNCC);
        a0.x += wA * vA0.x + wB * vB0.x;  a0.y += wA * vA0.y + wB * vB0.y;
        a1.x += wA * vA1.x + wB * vB1.x;  a1.y += wA * vA1.y + wB * vB1.y;
        a2.x += wA * vA2.x + wB * vB2.x;  a2.y += wA * vA2.y + wB * vB2.y;
        a3.x += wA * vA3.x + wB * vB3.x;  a3.y += wA * vA3.y + wB * vB3.y;
    }
    if (i < e) {
        int   cA = g_csr_col[i];
        float wA = g_csr_val[i];
        const float* pA = base + (size_t)cA * CC + c0;
        float2 vA0 = *(const float2*)(pA);
        float2 vA1 = *(const float2*)(pA + NNCC);
        float2 vA2 = *(const float2*)(pA + 2 * NNCC);
        float2 vA3 = *(const float2*)(pA + 3 * NNCC);
        a0.x += wA * vA0.x;  a0.y += wA * vA0.y;
        a1.x += wA * vA1.x;  a1.y += wA * vA1.y;
        a2.x += wA * vA2.x;  a2.y += wA * vA2.y;
        a3.x += wA * vA3.x;  a3.y += wA * vA3.y;
    }

    float bx = bias[c0], by = bias[c0 + 1];
    a0.x += bx; a0.y += by; a1.x += bx; a1.y += by;
    a2.x += bx; a2.y += by; a3.x += bx; a3.y += by;
    if (RELU) {
        a0.x = fmaxf(a0.x, 0.f); a0.y = fmaxf(a0.y, 0.f);
        a1.x = fmaxf(a1.x, 0.f); a1.y = fmaxf(a1.y, 0.f);
        a2.x = fmaxf(a2.x, 0.f); a2.y = fmaxf(a2.y, 0.f);
        a3.x = fmaxf(a3.x, 0.f); a3.y = fmaxf(a3.y, 0.f);
    }

    float* op = out + ((size_t)(bg * 4) * NN + r) * CC + c0;
    *(float2*)(op) = a0;
    *(float2*)(op + NNCC) = a1;
    *(float2*)(op + 2 * NNCC) = a2;
    *(float2*)(op + 3 * NNCC) = a3;

    if (BNOUT) {
        __shared__ float rsum[8 * 64];
        __shared__ float rsq[8 * 64];
        float sx = a0.x + a1.x + a2.x + a3.x;
        float sy = a0.y + a1.y + a2.y + a3.y;
        float qx = a0.x * a0.x + a1.x * a1.x + a2.x * a2.x + a3.x * a3.x;
        float qy = a0.y * a0.y + a1.y * a1.y + a2.y * a2.y + a3.y * a3.y;
        rsum[warp * 64 + c0] = sx; rsum[warp * 64 + c0 + 1] = sy;
        rsq[warp * 64 + c0] = qx;  rsq[warp * 64 + c0 + 1] = qy;
        __syncthreads();
        if (threadIdx.x < CC) {
            float ts = 0.f, tq = 0.f;
            #pragma unroll
            for (int j = 0; j < 8; j++) { ts += rsum[j * 64 + threadIdx.x]; tq += rsq[j * 64 + threadIdx.x]; }
            atomicAdd(&g_bnsum[slot * CC + threadIdx.x], (double)ts);
            atomicAdd(&g_bnsumsq[slot * CC + threadIdx.x], (double)tq);
        }
        bn_finalize_ticket(slot, gam, gridDim.x);
    }
}

// ---------------- top-k sort pooling + MLP layer-1 (merged, 1024 thr) --------
__device__ __forceinline__ void argmax_red32(float& v, int& i) {
    #pragma unroll
    for (int off = 16; off; off >>= 1) {
        float v2 = __shfl_down_sync(0xffffffffu, v, off);
        int   i2 = __shfl_down_sync(0xffffffffu, i, off);
        if (v2 > v || (v2 == v && i2 < i)) { v = v2; i = i2; }
    }
}

#define MSLC 8
#define SLW  ((FLATN + MSLC - 1) / MSLC)   // 781
__global__ void k_topk_mlp1(const float* __restrict__ x, const float* __restrict__ age,
                            const float* __restrict__ mW0, const float* __restrict__ mb0,
                            const float* __restrict__ be0, const float* __restrict__ be1) {
    __shared__ float sbuf[FLATN + MSLC * FH];  // phase1: key[5000]+wv[32]; phase2: flat+part
    __shared__ int   swi[32];
    __shared__ int   sel[KP];
    int b = blockIdx.x;
    int t = threadIdx.x;           // 0..1023
    int lane = t & 31, wid = t >> 5;

    // ---- phase 1: top-30 of h3[:, :, 63] (stable: val desc, idx asc) ----
    float* key = sbuf;
    float* swv = sbuf + NN;
    for (int n = t; n < NN; n += 1024)
        key[n] = g_h3[((size_t)b * NN + n) * CC + 63];
    __syncthreads();
    for (int it = 0; it < KP; it++) {
        float best = -INFINITY;
        int bidx = NN;
        for (int n = t; n < NN; n += 1024) {
            float v = key[n];
            if (v > best || (v == best && n < bidx)) { best = v; bidx = n; }
        }
        argmax_red32(best, bidx);
        if (lane == 0) { swv[wid] = best; swi[wid] = bidx; }
        __syncthreads();
        if (wid == 0) {
            float v = swv[lane];
            int i = swi[lane];
            argmax_red32(v, i);
            if (lane == 0) { sel[it] = i; key[i] = -INFINITY; }
        }
        __syncthreads();
    }

    // ---- phase 2: gather flat features (BN+relu applied to h1/h2) ----
    float* flat = sbuf;
    float* part = sbuf + FLATN;
    for (int i = t; i < KP * FTOT; i += 1024) {
        int k = i / FTOT;
        int f = i - k * FTOT;
        int n = sel[k];
        size_t bn = (size_t)b * NN + n;
        float v;
        if (f < DIN) {
            v = x[bn * DIN + f];
        } else if (f < DIN + CC) {
            int c = f - DIN;
            v = fmaxf((g_h1[bn * CC + c] - g_bnmu[c]) * g_bnsc[c] + be0[c], 0.f);
        } else if (f < DIN + 2 * CC) {
            int c = f - DIN - CC;
            v = fmaxf((g_h2[bn * CC + c] - g_bnmu[CC + c]) * g_bnsc[CC + c] + be1[c], 0.f);
        } else {
            v = g_h3[bn * CC + (f - DIN - 2 * CC)];
        }
        flat[i] = v;
    }
    if (t == 0) flat[KP * FTOT] = age[b];
    __syncthreads();

    // ---- MLP layer 1: 128 neurons x 8 slice-groups ----
    int tid = t & 127;
    int grp = t >> 7;
    int i0 = grp * SLW;
    int i1 = min(i0 + SLW, FLATN);
    float a[4];
    #pragma unroll
    for (int j = 0; j < 4; j++) a[j] = 0.f;
    int i = i0;
    for (; i + 4 <= i1; i += 4) {
        #pragma unroll
        for (int j = 0; j < 4; j++)
            a[j] += flat[i + j] * mW0[(size_t)(i + j) * FH + tid];
    }
    for (; i < i1; i++) a[0] += flat[i] * mW0[(size_t)i * FH + tid];
    part[grp * FH + tid] = (a[0] + a[1]) + (a[2] + a[3]);
    __syncthreads();

    if (grp == 0) {
        float acc = mb0[tid];
        #pragma unroll
        for (int g = 0; g < MSLC; g++) acc += part[g * FH + tid];
        g_hm[b * FH + tid] = fmaxf(acc, 0.f);
    }
}

__global__ void k_mlp2(const float* __restrict__ mW1, const float* __restrict__ mb1,
                       float* __restrict__ out) {
    int b = threadIdx.x;
    if (b >= NB) return;
    float a0 = mb1[0], a1 = mb1[1];
    #pragma unroll 4
    for (int j = 0; j < FH; j++) {
        float v = g_hm[b * FH + j];
        a0 += v * mW1[j * 2 + 0];
        a1 += v * mW1[j * 2 + 1];
    }
    float m = fmaxf(a0, a1);
    float lse = m + logf(expf(a0 - m) + expf(a1 - m));
    out[b * 2 + 0] = a0 - lse;
    out[b * 2 + 1] = a1 - lse;
}

// ---------------- driver ------------------------------------------------------
extern "C" void kernel_launch(void* const* d_in, const int* in_sizes, int n_in,
                              void* d_out, int out_size) {
    const float* x    = (const float*)d_in[0];
    const float* age  = (const float*)d_in[1];
    const float* attr = (const float*)d_in[2];
    const float* W0   = (const float*)d_in[3];
    const float* b0   = (const float*)d_in[4];
    const float* W1   = (const float*)d_in[5];
    const float* b1   = (const float*)d_in[6];
    const float* W2   = (const float*)d_in[7];
    const float* b2   = (const float*)d_in[8];
    const float* g0   = (const float*)d_in[9];
    const float* be0  = (const float*)d_in[10];
    const float* g1   = (const float*)d_in[11];
    const float* be1  = (const float*)d_in[12];
    const float* mW0  = (const float*)d_in[13];
    const float* mb0  = (const float*)d_in[14];
    const float* mW1  = (const float*)d_in[15];
    const float* mb1  = (const float*)d_in[16];
    const int*   erow = (const int*)d_in[17];
    const int*   ecol = (const int*)d_in[18];
    float* out = (float*)d_out;

    // Resolve REAL device addresses of scratch symbols (host-side query; capture-safe).
    float *p_ax = nullptr, *p_xw = nullptr, *p_h1 = nullptr, *p_h2 = nullptr, *p_h3 = nullptr;
    cudaGetSymbolAddress((void**)&p_ax, g_ax);
    cudaGetSymbolAddress((void**)&p_xw, g_xw);
    cudaGetSymbolAddress((void**)&p_h1, g_h1);
    cudaGetSymbolAddress((void**)&p_h2, g_h2);
    cudaGetSymbolAddress((void**)&p_h3, g_h3);

    // graph normalization + CSR build (4 launches)
    k_zero<<<(NN + 255) / 256, 256>>>();
    k_deg_accum<<<(NE + 255) / 256, 256>>>(attr, erow);
    k_dinv_scan<<<1, 1024>>>();
    k_build_csr<<<(NE + 255) / 256, 256>>>(attr, erow, ecol);

    const int spmm16_blocks = (NB * NN * 32 + 255) / 256;      // warp per (b,row)
    const int spmm4_blocks = (NN * (NB / 4) * 32 + 255) / 256; // warp per (row, bgrp) = 5000
    const int gemm_blocks = (int)(NTOT / 128);                 // 1250, exact

    // layer 0: aggregate (A X) then dense (AX)@W0 + b0; h1 RAW; BN0 stats fused
    k_spmm16<<<spmm16_blocks, 256>>>(x, p_ax);
    k_gemm_rb<DIN, true, false, true><<<gemm_blocks, 256>>>(p_ax, W0, b0, nullptr, 0, 0, g0, p_h1);

    // layer 1: xw = bnrelu0(h1) @ W1; h2 = A xw + b1 (BN1 stats fused)
    k_gemm_rb<CC, false, true, false><<<gemm_blocks, 256>>>(p_h1, W1, nullptr, be0, 0, 0, nullptr, p_xw);
    k_spmm4<false, true><<<spmm4_blocks, 256>>>(p_xw, b1, p_h2, 1, g1);

    // layer 2: xw = bnrelu1(h2) @ W2; h3 = relu(A xw + b2)
    k_gemm_rb<CC, false, true, false><<<gemm_blocks, 256>>>(p_h2, W2, nullptr, be1, 1, 0, nullptr, p_xw);
    k_spmm4<true, false><<<spmm4_blocks, 256>>>(p_xw, b2, p_h3, 0, nullptr);

    // sort pooling + MLP head
    k_topk_mlp1<<<NB, 1024>>>(x, age, mW0, mb0, be0, be1);
    k_mlp2<<<1, 32>>>(mW1, mb1, out);
}

// round 11
// speedup vs baseline: 1.3565x; 1.3565x over previous
#include <cuda_runtime.h>
#include <cuda_bf16.h>
#include <math.h>

#define NB 32
#define NN 5000
#define NE 80000
#define CC 64
#define DIN 16
#define KP 30
#define FH 128
#define FTOT 208
#define FLATN (KP*FTOT + 1)   // 6241
#define NTOT ((size_t)NB*NN)  // 160000 rows
#define BN_EPS 1e-5f

// ---------------- scratch (device globals; no allocation allowed) -------------
// Resolve with cudaGetSymbolAddress before passing to kernels (host shadows!).
__device__ float g_deg[NN];
__device__ float g_dinv[NN];
__device__ int   g_count[NN];
__device__ int   g_cursor[NN];
__device__ int   g_rowptr[NN + 1];
__device__ int2  g_csr[NE];            // packed (col, val-as-int)

__device__ float g_ax[NB * NN * DIN];  // layer-0 aggregated input (AX)
__device__ float g_xw[NB * NN * CC];   // GEMM output (spmm input)
__device__ float g_h1[NB * NN * CC];   // RAW (pre-BN) conv1 output
__device__ float g_h2[NB * NN * CC];   // RAW (pre-BN) conv2 output
__device__ float g_h3[NB * NN * CC];   // post-relu conv3 output

__device__ double g_bnsum[2 * CC];
__device__ double g_bnsumsq[2 * CC];
__device__ float  g_bnmu[2 * CC];
__device__ float  g_bnsc[2 * CC];
__device__ int    g_bnflag[2];
__device__ float  g_hm[NB * FH];

// ---------------- init: graph scratch + BN slots -----------------------------
__global__ void k_zero() {
    int i = blockIdx.x * blockDim.x + threadIdx.x;
    if (i < NN) { g_deg[i] = 0.f; g_count[i] = 0; g_cursor[i] = 0; }
    if (i < 2 * CC) { g_bnsum[i] = 0.0; g_bnsumsq[i] = 0.0; }
    if (i < 2) g_bnflag[i] = 0;
}

__global__ void k_deg_accum(const float* __restrict__ attr, const int* __restrict__ erow) {
    int e = blockIdx.x * blockDim.x + threadIdx.x;
    if (e < NE) {
        int r = erow[e];
        atomicAdd(&g_deg[r], attr[e]);
        atomicAdd(&g_count[r], 1);
    }
}

// dinv + exclusive scan, single block of 1024
__global__ void k_dinv_scan() {
    __shared__ int s[1024];
    int tid = threadIdx.x;
    for (int i = tid; i < NN; i += 1024) {
        float d = g_deg[i] + 1.0f;  // self loop weight 1
        g_dinv[i] = (d > 0.f) ? rsqrtf(fmaxf(d, 1e-12f)) : 0.f;
    }
    const int CH = 5; // 1024*5 >= 5000
    int base = tid * CH;
    int vals[CH];
    int sum = 0;
    #pragma unroll
    for (int j = 0; j < CH; j++) {
        int idx = base + j;
        int v = (idx < NN) ? g_count[idx] : 0;
        vals[j] = sum;
        sum += v;
    }
    s[tid] = sum;
    __syncthreads();
    for (int off = 1; off < 1024; off <<= 1) {
        int v = (tid >= off) ? s[tid - off] : 0;
        __syncthreads();
        s[tid] += v;
        __syncthreads();
    }
    int excl = (tid == 0) ? 0 : s[tid - 1];
    #pragma unroll
    for (int j = 0; j < CH; j++) {
        int idx = base + j;
        if (idx < NN) g_rowptr[idx] = excl + vals[j];
    }
    if (tid == 1023) g_rowptr[NN] = s[1023];
}

__global__ void k_build_csr(const float* __restrict__ attr,
                            const int* __restrict__ erow,
                            const int* __restrict__ ecol) {
    int e = blockIdx.x * blockDim.x + threadIdx.x;
    if (e < NE) {
        int r = erow[e], c = ecol[e];
        float nv = g_dinv[r] * attr[e] * g_dinv[c];
        int pos = g_rowptr[r] + atomicAdd(&g_cursor[r], 1);
        int2 p; p.x = c; p.y = __float_as_int(nv);
        g_csr[pos] = p;
    }
}

// ---------------- SPMM 16-channel (layer-0), 2 batches per warp --------------
// lane>>4 selects batch within the pair; lane&15 is the channel. Edge list
// (col/val) identical for both halves -> uniform broadcast loads.
__global__ void k_spmm16(const float* __restrict__ x, float* __restrict__ ax) {
    int gw = (blockIdx.x * blockDim.x + threadIdx.x) >> 5;  // 0 .. NN*NB/2-1
    int lane = threadIdx.x & 31;
    if (gw >= NN * (NB / 2)) return;
    int r = gw % NN;
    int bp = gw / NN;                  // batch pair 0..15
    int b = bp * 2 + (lane >> 4);
    int ch = lane & 15;

    const float* base = x + (size_t)b * NN * DIN;
    float di = g_dinv[r];
    float acc = base[(size_t)r * DIN + ch] * di * di;

    int s = g_rowptr[r];
    int e = g_rowptr[r + 1];
    int i = s;
    for (; i + 4 <= e; i += 4) {
        int2 e0 = g_csr[i + 0], e1 = g_csr[i + 1], e2 = g_csr[i + 2], e3 = g_csr[i + 3];
        acc += __int_as_float(e0.y) * base[(size_t)e0.x * DIN + ch]
             + __int_as_float(e1.y) * base[(size_t)e1.x * DIN + ch]
             + __int_as_float(e2.y) * base[(size_t)e2.x * DIN + ch]
             + __int_as_float(e3.y) * base[(size_t)e3.x * DIN + ch];
    }
    for (; i < e; i++) {
        int2 e0 = g_csr[i];
        acc += __int_as_float(e0.y) * base[(size_t)e0.x * DIN + ch];
    }
    ax[((size_t)b * NN + r) * DIN + ch] = acc;
}

// ---------------- dense GEMM (register-blocked): (M,K)@(K,64) -> (M,64) ------
// 256 threads = 16 ch-groups(4ch) x 16 row-slots; each row-slot owns 8 rows.
// BNIN: apply relu((v-mu)*sc+be) to input elements on load (K==CC).
template <int K, bool BIAS, bool BNIN>
__global__ void k_gemm_rb(const float* __restrict__ in, const float* __restrict__ W,
                          const float* __restrict__ bias, const float* __restrict__ be,
                          int slot, float* __restrict__ out) {
    __shared__ float Ws[K * CC];
    __shared__ float smu[CC], ssc[CC], sbe[CC];
    int tid = threadIdx.x;
    for (int i = tid; i < K * CC; i += 256) Ws[i] = W[i];
    if (BNIN && tid < CC) {
        smu[tid] = g_bnmu[slot * CC + tid];
        ssc[tid] = g_bnsc[slot * CC + tid];
        sbe[tid] = be[tid];
    }
    __syncthreads();

    int c = (tid & 15) * 4;
    int rslot = tid >> 4;
    size_t m0 = (size_t)blockIdx.x * 128 + (size_t)rslot * 8;

    float4 acc[8];
    #pragma unroll
    for (int r = 0; r < 8; r++) { acc[r].x = 0.f; acc[r].y = 0.f; acc[r].z = 0.f; acc[r].w = 0.f; }

    #pragma unroll
    for (int k = 0; k < K; k += 4) {
        float4 w0 = *(const float4*)(&Ws[(k + 0) * CC + c]);
        float4 w1 = *(const float4*)(&Ws[(k + 1) * CC + c]);
        float4 w2 = *(const float4*)(&Ws[(k + 2) * CC + c]);
        float4 w3 = *(const float4*)(&Ws[(k + 3) * CC + c]);
        float4 mu4, sc4, be4;
        if (BNIN) {
            mu4 = *(const float4*)(&smu[k]);
            sc4 = *(const float4*)(&ssc[k]);
            be4 = *(const float4*)(&sbe[k]);
        }
        #pragma unroll
        for (int r = 0; r < 8; r++) {
            float4 av = *(const float4*)(in + (m0 + r) * K + k);
            if (BNIN) {
                av.x = fmaxf((av.x - mu4.x) * sc4.x + be4.x, 0.f);
                av.y = fmaxf((av.y - mu4.y) * sc4.y + be4.y, 0.f);
                av.z = fmaxf((av.z - mu4.z) * sc4.z + be4.z, 0.f);
                av.w = fmaxf((av.w - mu4.w) * sc4.w + be4.w, 0.f);
            }
            acc[r].x += av.x * w0.x + av.y * w1.x + av.z * w2.x + av.w * w3.x;
            acc[r].y += av.x * w0.y + av.y * w1.y + av.z * w2.y + av.w * w3.y;
            acc[r].z += av.x * w0.z + av.y * w1.z + av.z * w2.z + av.w * w3.z;
            acc[r].w += av.x * w0.w + av.y * w1.w + av.z * w2.w + av.w * w3.w;
        }
    }
    float4 bv = make_float4(0.f, 0.f, 0.f, 0.f);
    if (BIAS) bv = *(const float4*)(bias + c);
    #pragma unroll
    for (int r = 0; r < 8; r++) {
        float4 o;
        o.x = acc[r].x + bv.x; o.y = acc[r].y + bv.y;
        o.z = acc[r].z + bv.z; o.w = acc[r].w + bv.w;
        *(float4*)(out + (m0 + r) * CC + c) = o;
    }
}

// ---------------- SPMM 64-channel (CSR gather): warp per (b,row) -------------
__global__ void k_spmm(const float* __restrict__ xw, const float* __restrict__ bias,
                       float* __restrict__ out, int fuse_relu) {
    int gw = (blockIdx.x * blockDim.x + threadIdx.x) >> 5;
    int lane = threadIdx.x & 31;
    if (gw >= NB * NN) return;
    int b = gw / NN;
    int r = gw - b * NN;
    int c0 = lane * 2;

    const float* base = xw + (size_t)b * NN * CC;
    float di = g_dinv[r];
    float sl = di * di;
    float2 acc = *(const float2*)(base + (size_t)r * CC + c0);
    acc.x *= sl; acc.y *= sl;

    int s = g_rowptr[r];
    int e = g_rowptr[r + 1];
    int i = s;
    for (; i + 4 <= e; i += 4) {
        int2 e0 = g_csr[i + 0], e1 = g_csr[i + 1], e2 = g_csr[i + 2], e3 = g_csr[i + 3];
        float wA = __int_as_float(e0.y), wB = __int_as_float(e1.y);
        float wC = __int_as_float(e2.y), wD = __int_as_float(e3.y);
        float2 vA = *(const float2*)(base + (size_t)e0.x * CC + c0);
        float2 vB = *(const float2*)(base + (size_t)e1.x * CC + c0);
        float2 vC = *(const float2*)(base + (size_t)e2.x * CC + c0);
        float2 vD = *(const float2*)(base + (size_t)e3.x * CC + c0);
        acc.x += wA * vA.x + wB * vB.x + wC * vC.x + wD * vD.x;
        acc.y += wA * vA.y + wB * vB.y + wC * vC.y + wD * vD.y;
    }
    for (; i < e; i++) {
        int2 e0 = g_csr[i];
        float wA = __int_as_float(e0.y);
        float2 vA = *(const float2*)(base + (size_t)e0.x * CC + c0);
        acc.x += wA * vA.x;
        acc.y += wA * vA.y;
    }
    acc.x += bias[c0];
    acc.y += bias[c0 + 1];
    if (fuse_relu) { acc.x = fmaxf(acc.x, 0.f); acc.y = fmaxf(acc.y, 0.f); }
    *(float2*)(out + ((size_t)b * NN + r) * CC + c0) = acc;
}

// ---------------- BatchNorm stats + last-block finalize ----------------------
// block = 256 threads = 64 ch x 4 row-slots; block covers 256 rows.
__global__ void k_bn_stat(const float* __restrict__ h, int slot,
                          const float* __restrict__ gam) {
    int c = threadIdx.x & 63;
    int rs = threadIdx.x >> 6;
    size_t row0 = (size_t)blockIdx.x * 256;
    float s = 0.f, s2 = 0.f;
    for (int j = rs; j < 256; j += 4) {
        size_t row = row0 + j;
        if (row < NTOT) {
            float v = h[row * CC + c];
            s += v; s2 += v * v;
        }
    }
    __shared__ float ss[256], ss2[256];
    __shared__ int last;
    ss[threadIdx.x] = s; ss2[threadIdx.x] = s2;
    __syncthreads();
    if (rs == 0) {
        double ds  = (double)ss[c]  + (double)ss[64 + c]  + (double)ss[128 + c]  + (double)ss[192 + c];
        double ds2 = (double)ss2[c] + (double)ss2[64 + c] + (double)ss2[128 + c] + (double)ss2[192 + c];
        atomicAdd(&g_bnsum[slot * CC + c], ds);
        atomicAdd(&g_bnsumsq[slot * CC + c], ds2);
        __threadfence();
    }
    __syncthreads();
    if (threadIdx.x == 0) {
        int t = atomicAdd(&g_bnflag[slot], 1);
        last = (t == (int)gridDim.x - 1) ? 1 : 0;
    }
    __syncthreads();
    if (last && threadIdx.x < CC) {
        __threadfence();
        const double invN = 1.0 / (double)(NB * NN);
        double mu = g_bnsum[slot * CC + threadIdx.x] * invN;
        double var = g_bnsumsq[slot * CC + threadIdx.x] * invN - mu * mu;
        g_bnmu[slot * CC + threadIdx.x] = (float)mu;
        g_bnsc[slot * CC + threadIdx.x] = rsqrtf((float)var + BN_EPS) * gam[threadIdx.x];
    }
}

// ---------------- top-k sort pooling + MLP layer-1 (merged, 1024 thr) --------
__device__ __forceinline__ void argmax_red32(float& v, int& i) {
    #pragma unroll
    for (int off = 16; off; off >>= 1) {
        float v2 = __shfl_down_sync(0xffffffffu, v, off);
        int   i2 = __shfl_down_sync(0xffffffffu, i, off);
        if (v2 > v || (v2 == v && i2 < i)) { v = v2; i = i2; }
    }
}

#define MSLC 8
#define SLW  ((FLATN + MSLC - 1) / MSLC)   // 781
__global__ void k_topk_mlp1(const float* __restrict__ x, const float* __restrict__ age,
                            const float* __restrict__ mW0, const float* __restrict__ mb0,
                            const float* __restrict__ be0, const float* __restrict__ be1) {
    __shared__ float sbuf[FLATN + MSLC * FH];  // phase1: key[5000]+wv[32]; phase2: flat+part
    __shared__ int   swi[32];
    __shared__ int   sel[KP];
    int b = blockIdx.x;
    int t = threadIdx.x;           // 0..1023
    int lane = t & 31, wid = t >> 5;

    // ---- phase 1: top-30 of h3[:, :, 63] (stable: val desc, idx asc) ----
    float* key = sbuf;
    float* swv = sbuf + NN;
    for (int n = t; n < NN; n += 1024)
        key[n] = g_h3[((size_t)b * NN + n) * CC + 63];
    __syncthreads();
    for (int it = 0; it < KP; it++) {
        float best = -INFINITY;
        int bidx = NN;
        for (int n = t; n < NN; n += 1024) {
            float v = key[n];
            if (v > best || (v == best && n < bidx)) { best = v; bidx = n; }
        }
        argmax_red32(best, bidx);
        if (lane == 0) { swv[wid] = best; swi[wid] = bidx; }
        __syncthreads();
        if (wid == 0) {
            float v = swv[lane];
            int i = swi[lane];
            argmax_red32(v, i);
            if (lane == 0) { sel[it] = i; key[i] = -INFINITY; }
        }
        __syncthreads();
    }

    // ---- phase 2: gather flat features (BN+relu applied to h1/h2) ----
    float* flat = sbuf;
    float* part = sbuf + FLATN;
    for (int i = t; i < KP * FTOT; i += 1024) {
        int k = i / FTOT;
        int f = i - k * FTOT;
        int n = sel[k];
        size_t bn = (size_t)b * NN + n;
        float v;
        if (f < DIN) {
            v = x[bn * DIN + f];
        } else if (f < DIN + CC) {
            int c = f - DIN;
            v = fmaxf((g_h1[bn * CC + c] - g_bnmu[c]) * g_bnsc[c] + be0[c], 0.f);
        } else if (f < DIN + 2 * CC) {
            int c = f - DIN - CC;
            v = fmaxf((g_h2[bn * CC + c] - g_bnmu[CC + c]) * g_bnsc[CC + c] + be1[c], 0.f);
        } else {
            v = g_h3[bn * CC + (f - DIN - 2 * CC)];
        }
        flat[i] = v;
    }
    if (t == 0) flat[KP * FTOT] = age[b];
    __syncthreads();

    // ---- MLP layer 1: 128 neurons x 8 slice-groups ----
    int tid = t & 127;
    int grp = t >> 7;
    int i0 = grp * SLW;
    int i1 = min(i0 + SLW, FLATN);
    float a[4];
    #pragma unroll
    for (int j = 0; j < 4; j++) a[j] = 0.f;
    int i = i0;
    for (; i + 4 <= i1; i += 4) {
        #pragma unroll
        for (int j = 0; j < 4; j++)
            a[j] += flat[i + j] * mW0[(size_t)(i + j) * FH + tid];
    }
    for (; i < i1; i++) a[0] += flat[i] * mW0[(size_t)i * FH + tid];
    part[grp * FH + tid] = (a[0] + a[1]) + (a[2] + a[3]);
    __syncthreads();

    if (grp == 0) {
        float acc = mb0[tid];
        #pragma unroll
        for (int g = 0; g < MSLC; g++) acc += part[g * FH + tid];
        g_hm[b * FH + tid] = fmaxf(acc, 0.f);
    }
}

__global__ void k_mlp2(const float* __restrict__ mW1, const float* __restrict__ mb1,
                       float* __restrict__ out) {
    int b = threadIdx.x;
    if (b >= NB) return;
    float a0 = mb1[0], a1 = mb1[1];
    #pragma unroll 4
    for (int j = 0; j < FH; j++) {
        float v = g_hm[b * FH + j];
        a0 += v * mW1[j * 2 + 0];
        a1 += v * mW1[j * 2 + 1];
    }
    float m = fmaxf(a0, a1);
    float lse = m + logf(expf(a0 - m) + expf(a1 - m));
    out[b * 2 + 0] = a0 - lse;
    out[b * 2 + 1] = a1 - lse;
}

// ---------------- driver ------------------------------------------------------
extern "C" void kernel_launch(void* const* d_in, const int* in_sizes, int n_in,
                              void* d_out, int out_size) {
    const float* x    = (const float*)d_in[0];
    const float* age  = (const float*)d_in[1];
    const float* attr = (const float*)d_in[2];
    const float* W0   = (const float*)d_in[3];
    const float* b0   = (const float*)d_in[4];
    const float* W1   = (const float*)d_in[5];
    const float* b1   = (const float*)d_in[6];
    const float* W2   = (const float*)d_in[7];
    const float* b2   = (const float*)d_in[8];
    const float* g0   = (const float*)d_in[9];
    const float* be0  = (const float*)d_in[10];
    const float* g1   = (const float*)d_in[11];
    const float* be1  = (const float*)d_in[12];
    const float* mW0  = (const float*)d_in[13];
    const float* mb0  = (const float*)d_in[14];
    const float* mW1  = (const float*)d_in[15];
    const float* mb1  = (const float*)d_in[16];
    const int*   erow = (const int*)d_in[17];
    const int*   ecol = (const int*)d_in[18];
    float* out = (float*)d_out;

    // Resolve REAL device addresses of scratch symbols (host-side query; capture-safe).
    float *p_ax = nullptr, *p_xw = nullptr, *p_h1 = nullptr, *p_h2 = nullptr, *p_h3 = nullptr;
    cudaGetSymbolAddress((void**)&p_ax, g_ax);
    cudaGetSymbolAddress((void**)&p_xw, g_xw);
    cudaGetSymbolAddress((void**)&p_h1, g_h1);
    cudaGetSymbolAddress((void**)&p_h2, g_h2);
    cudaGetSymbolAddress((void**)&p_h3, g_h3);

    // graph normalization + CSR build (4 launches)
    k_zero<<<(NN + 255) / 256, 256>>>();
    k_deg_accum<<<(NE + 255) / 256, 256>>>(attr, erow);
    k_dinv_scan<<<1, 1024>>>();
    k_build_csr<<<(NE + 255) / 256, 256>>>(attr, erow, ecol);

    const int spmm16_blocks = (NN * (NB / 2) * 32 + 255) / 256; // 2 batches per warp
    const int spmm_blocks = (NB * NN * 32 + 255) / 256;         // warp per (b,row)
    const int gemm_blocks = (int)(NTOT / 128);                  // 1250, exact
    const int bn_stat_blocks = (int)((NTOT + 255) / 256);       // 625, exact

    // layer 0: aggregate (A X) then dense (AX)@W0 + b0; h1 stored RAW
    k_spmm16<<<spmm16_blocks, 256>>>(x, p_ax);
    k_gemm_rb<DIN, true, false><<<gemm_blocks, 256>>>(p_ax, W0, b0, nullptr, 0, p_h1);
    k_bn_stat<<<bn_stat_blocks, 256>>>(p_h1, 0, g0);

    // layer 1: xw = bnrelu0(h1) @ W1 (BN fused into input load); h2 RAW
    k_gemm_rb<CC, false, true><<<gemm_blocks, 256>>>(p_h1, W1, nullptr, be0, 0, p_xw);
    k_spmm<<<spmm_blocks, 256>>>(p_xw, b1, p_h2, 0);
    k_bn_stat<<<bn_stat_blocks, 256>>>(p_h2, 1, g1);

    // layer 2: xw = bnrelu1(h2) @ W2; h3 = relu(A xw + b2)
    k_gemm_rb<CC, false, true><<<gemm_blocks, 256>>>(p_h2, W2, nullptr, be1, 1, p_xw);
    k_spmm<<<spmm_blocks, 256>>>(p_xw, b2, p_h3, 1);

    // sort pooling + MLP head
    k_topk_mlp1<<<NB, 1024>>>(x, age, mW0, mb0, be0, be1);
    k_mlp2<<<1, 32>>>(mW1, mb1, out);
}